// round 7
// baseline (speedup 1.0000x reference)
#include <cuda_runtime.h>
#include <math.h>

#define CCH   256
#define HW    384
#define NPIX  (HW*HW)        // 147456 elems per channel
#define NQ    (NPIX/4)       // 36864 float4 per channel
#define QPR   (HW/4)         // 96 float4 per row
#define NBLK  128            // row-triples per channel (384/3)
#define INVN  (1.0f/(382.0f*382.0f))

// Stats accumulators. g_tot/g_col are atomic targets (zeroed by init_kernel);
// g_row/g_corn have unique owner blocks (plain stores, all slots written).
__device__ float g_tot [2][CCH];
__device__ float g_col [2][CCH][4];      // col sums, classes {0,1,382,383}
__device__ float g_row [2][CCH][4];      // row sums, classes {0,1,382,383}
__device__ float g_corn[2][CCH][16];     // [row class][col class]
__device__ float g_cf  [2][CCH];

__global__ void init_kernel() {
    int i = blockIdx.x * 256 + threadIdx.x;
    if (i < 2 * CCH)     ((float*)g_tot)[i] = 0.0f;
    if (i < 2 * CCH * 4) ((float*)g_col)[i] = 0.0f;
}

// ---------------------------------------------------------------------------
// Kernel 1: stats, combine-shaped. grid = (NBLK, 2 inputs, CCH),
// block = (96, 3). One float4 load per thread; block covers exactly 3 rows.
// Warp w holds row threadIdx.y = w/3 (96 = 3 warps per row).
// Border rows {0,1} only in blockIdx.x==0; {382,383} only in blockIdx.x==127.
// ---------------------------------------------------------------------------
__global__ void __launch_bounds__(288) stats_kernel(const float* __restrict__ in1,
                                                    const float* __restrict__ in2) {
    const int blk   = blockIdx.x;
    const int which = blockIdx.y;
    const int c     = blockIdx.z;
    const int x     = threadIdx.x;     // 0..95  (column quad)
    const int y     = threadIdx.y;     // 0..2   (row within triple)
    const int tid   = y * 96 + x;

    __shared__ float colsh[4];
    __shared__ float red[9];
    if (tid < 4) colsh[tid] = 0.0f;

    const float4* base = ((const float4*)(which ? in2 : in1)) + (size_t)c * NQ;
    float4 v = base[(size_t)blk * 288 + tid];
    float s = (v.x + v.y) + (v.z + v.w);

    // corners: plain stores by unique owners
    if (blk == 0 && y < 2) {
        if (x == 0)  { g_corn[which][c][y*4 + 0] = v.x; g_corn[which][c][y*4 + 1] = v.y; }
        if (x == 95) { g_corn[which][c][y*4 + 2] = v.z; g_corn[which][c][y*4 + 3] = v.w; }
    }
    if (blk == NBLK - 1 && y >= 1) {   // rows 382 (y=1) -> class 2, 383 (y=2) -> class 3
        int rc = y + 1;
        if (x == 0)  { g_corn[which][c][rc*4 + 0] = v.x; g_corn[which][c][rc*4 + 1] = v.y; }
        if (x == 95) { g_corn[which][c][rc*4 + 2] = v.z; g_corn[which][c][rc*4 + 3] = v.w; }
    }

    __syncthreads();                   // colsh init visible

    if (x == 0)  { atomicAdd(&colsh[0], v.x); atomicAdd(&colsh[1], v.y); }
    if (x == 95) { atomicAdd(&colsh[2], v.z); atomicAdd(&colsh[3], v.w); }

    // warp reduce (warps align with rows)
    float t = s;
    #pragma unroll
    for (int off = 16; off > 0; off >>= 1)
        t += __shfl_down_sync(0xffffffffu, t, off);
    int warp = tid >> 5, lane = tid & 31;
    if (lane == 0) red[warp] = t;
    __syncthreads();

    if (tid == 0) {
        float T = 0.0f;
        #pragma unroll
        for (int w = 0; w < 9; w++) T += red[w];
        atomicAdd(&g_tot[which][c], T);
        if (blk == 0) {
            g_row[which][c][0] = red[0] + red[1] + red[2];   // row 0
            g_row[which][c][1] = red[3] + red[4] + red[5];   // row 1
        }
        if (blk == NBLK - 1) {
            g_row[which][c][2] = red[3] + red[4] + red[5];   // row 382
            g_row[which][c][3] = red[6] + red[7] + red[8];   // row 383
        }
    }
    if (tid < 4) atomicAdd(&g_col[which][c][tid], colsh[tid]);
}

// ---------------------------------------------------------------------------
// Kernel 2: finalize (stats -> 9 window sums) fused with per-oc matvec,
// sigmoid, branch flags -> per-channel combine coefficients.
// ---------------------------------------------------------------------------
__global__ void __launch_bounds__(256) coef_kernel(const float* __restrict__ W,
                                                   const float* __restrict__ b) {
    const int oc = blockIdx.x;
    const int ic = threadIdx.x;

    // build S[which][9] for this input-channel
    float S[2][9];
    const int ER[3][2] = { {2,3}, {0,3}, {0,1} };
    #pragma unroll
    for (int w = 0; w < 2; w++) {
        float T = g_tot[w][ic];
        float rs0 = g_row[w][ic][0], rs1 = g_row[w][ic][1],
              rs2 = g_row[w][ic][2], rs3 = g_row[w][ic][3];
        float cs0 = g_col[w][ic][0], cs1 = g_col[w][ic][1],
              cs2 = g_col[w][ic][2], cs3 = g_col[w][ic][3];
        float Rex[3] = { rs2+rs3, rs0+rs3, rs0+rs1 };
        float Cex[3] = { cs2+cs3, cs0+cs3, cs0+cs1 };
        #pragma unroll
        for (int kh = 0; kh < 3; kh++)
            #pragma unroll
            for (int kw = 0; kw < 3; kw++) {
                float cor = 0.0f;
                #pragma unroll
                for (int i = 0; i < 2; i++)
                    #pragma unroll
                    for (int j = 0; j < 2; j++)
                        cor += g_corn[w][ic][ER[kh][i]*4 + ER[kw][j]];
                S[w][kh*3 + kw] = T - Rex[kh] - Cex[kw] + cor;
            }
    }

    const float* wrow = W + (size_t)oc * CCH * 9 + ic * 9;
    float d1 = 0.0f, d2 = 0.0f;
    #pragma unroll
    for (int k = 0; k < 9; k++) {
        float w = wrow[k];
        d1 += w * S[0][k];
        d2 += w * S[1][k];
    }
    #pragma unroll
    for (int off = 16; off > 0; off >>= 1) {
        d1 += __shfl_down_sync(0xffffffffu, d1, off);
        d2 += __shfl_down_sync(0xffffffffu, d2, off);
    }
    __shared__ float s1[8], s2[8];
    int warp = ic >> 5, lane = ic & 31;
    if (lane == 0) { s1[warp] = d1; s2[warp] = d2; }
    __syncthreads();
    if (ic == 0) {
        float D1 = 0.0f, D2 = 0.0f;
        #pragma unroll
        for (int w = 0; w < 8; w++) { D1 += s1[w]; D2 += s2[w]; }
        float bb = b[oc];
        float m1 = bb + D1 * INVN;
        float m2 = bb + D2 * INVN;
        float m3 = bb + (D1 + D2) * INVN;
        float x1 = 1.0f / (1.0f + expf(-m1));
        float x2 = 1.0f / (1.0f + expf(-m2));
        float x3 = 1.0f / (1.0f + expf(-m3));
        bool c1 = (x1 >= x2);
        bool c2 = (x1 <= x2);
        float a1 = (c1 && (x1 >= x3)) ? 1.0f : 0.0f;
        float a2 = (c2 && (x2 >= x3)) ? 1.0f : 0.0f;
        float a3 = ((c1 && (x1 < x3)) || (c2 && (x2 < x3))) ? 1.0f : 0.0f;
        g_cf[0][oc] = a1 + a3;
        g_cf[1][oc] = a2 + a3;
    }
}

// ---------------------------------------------------------------------------
// Kernel 3: out = k1[ch]*in1 + k2[ch]*in2. Channels iterated in REVERSE so the
// channels stats touched last (still L2-resident) are read first. Loads .cs
// (hit-then-evict), stores .cs (don't pollute L2 read residency).
// ---------------------------------------------------------------------------
__global__ void __launch_bounds__(256) combine_kernel(const float4* __restrict__ in1,
                                                      const float4* __restrict__ in2,
                                                      float4* __restrict__ out) {
    const int bpc   = NQ / 256;                    // 144 blocks per channel
    const int ch    = (CCH - 1) - blockIdx.x / bpc;
    const int inCh  = (blockIdx.x % bpc) * 256 + threadIdx.x;
    const size_t idx = (size_t)ch * NQ + inCh;
    const float k1 = g_cf[0][ch];
    const float k2 = g_cf[1][ch];
    float4 a = __ldcs(in1 + idx);
    float4 b = __ldcs(in2 + idx);
    float4 o;
    o.x = k1 * a.x + k2 * b.x;
    o.y = k1 * a.y + k2 * b.y;
    o.z = k1 * a.z + k2 * b.z;
    o.w = k1 * a.w + k2 * b.w;
    __stcs(out + idx, o);
}

extern "C" void kernel_launch(void* const* d_in, const int* in_sizes, int n_in,
                              void* d_out, int out_size) {
    const float* in1 = (const float*)d_in[0];
    const float* in2 = (const float*)d_in[1];
    const float* W   = (const float*)d_in[2];
    const float* b   = (const float*)d_in[3];
    float* out = (float*)d_out;

    init_kernel<<<8, 256>>>();
    stats_kernel<<<dim3(NBLK, 2, CCH), dim3(96, 3)>>>(in1, in2);
    coef_kernel<<<CCH, 256>>>(W, b);
    combine_kernel<<<CCH * (NQ / 256), 256>>>((const float4*)in1,
                                              (const float4*)in2,
                                              (float4*)out);
}

// round 8
// speedup vs baseline: 1.0057x; 1.0057x over previous
#include <cuda_runtime.h>
#include <math.h>

#define CCH   256
#define HW    384
#define NPIX  (HW*HW)        // 147456 elems per channel
#define NQ    (NPIX/4)       // 36864 float4 per channel
#define QPR   (HW/4)         // 96 float4 per row
#define NBLK  128            // row-triples per channel (384/3)
#define INVN  (1.0f/(382.0f*382.0f))

// Stats accumulators. g_tot/g_col are atomic targets (zeroed by init_kernel);
// g_row/g_corn have unique owner blocks (plain stores, all slots written).
__device__ float g_tot [2][CCH];
__device__ float g_col [2][CCH][4];      // col sums, classes {0,1,382,383}
__device__ float g_row [2][CCH][4];      // row sums, classes {0,1,382,383}
__device__ float g_corn[2][CCH][16];     // [row class][col class]
__device__ float g_cf  [2][CCH];

__global__ void init_kernel() {
    int i = blockIdx.x * 256 + threadIdx.x;
    if (i < 2 * CCH)     ((float*)g_tot)[i] = 0.0f;
    if (i < 2 * CCH * 4) ((float*)g_col)[i] = 0.0f;
}

// ---------------------------------------------------------------------------
// Kernel 1: stats, combine-shaped. grid = (NBLK, 2 inputs, CCH),
// block = (96, 3). One float4 load per thread; block covers exactly 3 rows.
// Warp w holds row threadIdx.y = w/3 (96 = 3 warps per row).
// Border rows {0,1} only in blockIdx.x==0; {382,383} only in blockIdx.x==127.
// ---------------------------------------------------------------------------
__global__ void __launch_bounds__(288) stats_kernel(const float* __restrict__ in1,
                                                    const float* __restrict__ in2) {
    const int blk   = blockIdx.x;
    const int which = blockIdx.y;
    const int c     = blockIdx.z;
    const int x     = threadIdx.x;     // 0..95  (column quad)
    const int y     = threadIdx.y;     // 0..2   (row within triple)
    const int tid   = y * 96 + x;

    __shared__ float colsh[4];
    __shared__ float red[9];
    if (tid < 4) colsh[tid] = 0.0f;

    const float4* base = ((const float4*)(which ? in2 : in1)) + (size_t)c * NQ;
    float4 v = base[(size_t)blk * 288 + tid];
    float s = (v.x + v.y) + (v.z + v.w);

    // corners: plain stores by unique owners
    if (blk == 0 && y < 2) {
        if (x == 0)  { g_corn[which][c][y*4 + 0] = v.x; g_corn[which][c][y*4 + 1] = v.y; }
        if (x == 95) { g_corn[which][c][y*4 + 2] = v.z; g_corn[which][c][y*4 + 3] = v.w; }
    }
    if (blk == NBLK - 1 && y >= 1) {   // rows 382 (y=1) -> class 2, 383 (y=2) -> class 3
        int rc = y + 1;
        if (x == 0)  { g_corn[which][c][rc*4 + 0] = v.x; g_corn[which][c][rc*4 + 1] = v.y; }
        if (x == 95) { g_corn[which][c][rc*4 + 2] = v.z; g_corn[which][c][rc*4 + 3] = v.w; }
    }

    __syncthreads();                   // colsh init visible

    if (x == 0)  { atomicAdd(&colsh[0], v.x); atomicAdd(&colsh[1], v.y); }
    if (x == 95) { atomicAdd(&colsh[2], v.z); atomicAdd(&colsh[3], v.w); }

    // warp reduce (warps align with rows)
    float t = s;
    #pragma unroll
    for (int off = 16; off > 0; off >>= 1)
        t += __shfl_down_sync(0xffffffffu, t, off);
    int warp = tid >> 5, lane = tid & 31;
    if (lane == 0) red[warp] = t;
    __syncthreads();

    if (tid == 0) {
        float T = 0.0f;
        #pragma unroll
        for (int w = 0; w < 9; w++) T += red[w];
        atomicAdd(&g_tot[which][c], T);
        if (blk == 0) {
            g_row[which][c][0] = red[0] + red[1] + red[2];   // row 0
            g_row[which][c][1] = red[3] + red[4] + red[5];   // row 1
        }
        if (blk == NBLK - 1) {
            g_row[which][c][2] = red[3] + red[4] + red[5];   // row 382
            g_row[which][c][3] = red[6] + red[7] + red[8];   // row 383
        }
    }
    if (tid < 4) atomicAdd(&g_col[which][c][tid], colsh[tid]);
}

// ---------------------------------------------------------------------------
// Kernel 2: finalize (stats -> 9 window sums) fused with per-oc matvec,
// sigmoid, branch flags -> per-channel combine coefficients.
// ---------------------------------------------------------------------------
__global__ void __launch_bounds__(256) coef_kernel(const float* __restrict__ W,
                                                   const float* __restrict__ b) {
    const int oc = blockIdx.x;
    const int ic = threadIdx.x;

    // build S[which][9] for this input-channel
    float S[2][9];
    const int ER[3][2] = { {2,3}, {0,3}, {0,1} };
    #pragma unroll
    for (int w = 0; w < 2; w++) {
        float T = g_tot[w][ic];
        float rs0 = g_row[w][ic][0], rs1 = g_row[w][ic][1],
              rs2 = g_row[w][ic][2], rs3 = g_row[w][ic][3];
        float cs0 = g_col[w][ic][0], cs1 = g_col[w][ic][1],
              cs2 = g_col[w][ic][2], cs3 = g_col[w][ic][3];
        float Rex[3] = { rs2+rs3, rs0+rs3, rs0+rs1 };
        float Cex[3] = { cs2+cs3, cs0+cs3, cs0+cs1 };
        #pragma unroll
        for (int kh = 0; kh < 3; kh++)
            #pragma unroll
            for (int kw = 0; kw < 3; kw++) {
                float cor = 0.0f;
                #pragma unroll
                for (int i = 0; i < 2; i++)
                    #pragma unroll
                    for (int j = 0; j < 2; j++)
                        cor += g_corn[w][ic][ER[kh][i]*4 + ER[kw][j]];
                S[w][kh*3 + kw] = T - Rex[kh] - Cex[kw] + cor;
            }
    }

    const float* wrow = W + (size_t)oc * CCH * 9 + ic * 9;
    float d1 = 0.0f, d2 = 0.0f;
    #pragma unroll
    for (int k = 0; k < 9; k++) {
        float w = wrow[k];
        d1 += w * S[0][k];
        d2 += w * S[1][k];
    }
    #pragma unroll
    for (int off = 16; off > 0; off >>= 1) {
        d1 += __shfl_down_sync(0xffffffffu, d1, off);
        d2 += __shfl_down_sync(0xffffffffu, d2, off);
    }
    __shared__ float s1[8], s2[8];
    int warp = ic >> 5, lane = ic & 31;
    if (lane == 0) { s1[warp] = d1; s2[warp] = d2; }
    __syncthreads();
    if (ic == 0) {
        float D1 = 0.0f, D2 = 0.0f;
        #pragma unroll
        for (int w = 0; w < 8; w++) { D1 += s1[w]; D2 += s2[w]; }
        float bb = b[oc];
        float m1 = bb + D1 * INVN;
        float m2 = bb + D2 * INVN;
        float m3 = bb + (D1 + D2) * INVN;
        float x1 = 1.0f / (1.0f + expf(-m1));
        float x2 = 1.0f / (1.0f + expf(-m2));
        float x3 = 1.0f / (1.0f + expf(-m3));
        bool c1 = (x1 >= x2);
        bool c2 = (x1 <= x2);
        float a1 = (c1 && (x1 >= x3)) ? 1.0f : 0.0f;
        float a2 = (c2 && (x2 >= x3)) ? 1.0f : 0.0f;
        float a3 = ((c1 && (x1 < x3)) || (c2 && (x2 < x3))) ? 1.0f : 0.0f;
        g_cf[0][oc] = a1 + a3;
        g_cf[1][oc] = a2 + a3;
    }
}

// ---------------------------------------------------------------------------
// Kernel 3: out = k1[ch]*in1 + k2[ch]*in2. Channels iterated in REVERSE so the
// channels stats touched last (still L2-resident) are read first. Loads .cs
// (hit-then-evict), stores .cs (don't pollute L2 read residency).
// ---------------------------------------------------------------------------
__global__ void __launch_bounds__(256) combine_kernel(const float4* __restrict__ in1,
                                                      const float4* __restrict__ in2,
                                                      float4* __restrict__ out) {
    const int bpc   = NQ / 256;                    // 144 blocks per channel
    const int ch    = (CCH - 1) - blockIdx.x / bpc;
    const int inCh  = (blockIdx.x % bpc) * 256 + threadIdx.x;
    const size_t idx = (size_t)ch * NQ + inCh;
    const float k1 = g_cf[0][ch];
    const float k2 = g_cf[1][ch];
    float4 a = __ldcs(in1 + idx);
    float4 b = __ldcs(in2 + idx);
    float4 o;
    o.x = k1 * a.x + k2 * b.x;
    o.y = k1 * a.y + k2 * b.y;
    o.z = k1 * a.z + k2 * b.z;
    o.w = k1 * a.w + k2 * b.w;
    __stcs(out + idx, o);
}

extern "C" void kernel_launch(void* const* d_in, const int* in_sizes, int n_in,
                              void* d_out, int out_size) {
    const float* in1 = (const float*)d_in[0];
    const float* in2 = (const float*)d_in[1];
    const float* W   = (const float*)d_in[2];
    const float* b   = (const float*)d_in[3];
    float* out = (float*)d_out;

    init_kernel<<<8, 256>>>();
    stats_kernel<<<dim3(NBLK, 2, CCH), dim3(96, 3)>>>(in1, in2);
    coef_kernel<<<CCH, 256>>>(W, b);
    combine_kernel<<<CCH * (NQ / 256), 256>>>((const float4*)in1,
                                              (const float4*)in2,
                                              (float4*)out);
}

// round 9
// speedup vs baseline: 1.2174x; 1.2105x over previous
#include <cuda_runtime.h>
#include <math.h>

#define CCH   256
#define HW    384
#define NPIX  (HW*HW)        // 147456 elems per channel
#define NQ    (NPIX/4)       // 36864 float4 per channel
#define QPR   (HW/4)         // 96 float4 per row
#define INVN  (1.0f/(382.0f*382.0f))

// Scratch: window sums S[input][channel][9] and final per-channel coefficients.
__device__ float g_S[2][CCH][9];
__device__ float g_cf[2][CCH];

// ---------------------------------------------------------------------------
// Kernel 1: per-(input, channel) statistics -> 9 window sums.
// 384 threads: r0 = tid/96 in [0,4), q = tid%96. Row = 4j + r0, j in [0,96).
// DUAL STREAM: stream A covers j in [0,48) (rows 0..191), stream B covers
// j in [48,96) (rows 192..383). Two independent pointers + accumulator chains
// per thread -> doubled MLP, halved FADD dependency chains.
// Border rows: A's j=0 peel (rows 0,1 when r0<2), B's j=95 peel (rows 382,383
// when r0>=2). Column predicates (q==0 / q==95) are loop-invariant.
// ---------------------------------------------------------------------------
__global__ void __launch_bounds__(384) stats_kernel(const float* __restrict__ in1,
                                                    const float* __restrict__ in2) {
    const int c     = blockIdx.x;
    const int which = blockIdx.y;
    const float4* x = ((const float4*)(which ? in2 : in1)) + (size_t)c * NQ;

    const int tid = threadIdx.x;
    const int r0  = tid / 96;          // 0..3
    const int q   = tid - r0 * 96;     // 0..95
    const bool q0  = (q == 0);
    const bool q95 = (q == 95);

    __shared__ float corn[16];         // [row-class][col-class]
    __shared__ float rowsh[4];         // row sums for rows 0,1,382,383
    __shared__ float colsh[4];         // col sums for cols 0,1,382,383
    __shared__ float red[12];          // per-warp totals
    if (tid < 4) { rowsh[tid] = 0.0f; colsh[tid] = 0.0f; }

    const float4* pA = x + (size_t)(r0 * 96 + q);            // row r0
    const float4* pB = x + (size_t)((192 + r0) * 96 + q);    // row 192+r0

    float totA = 0.0f, totB = 0.0f;
    float c0 = 0.0f, c1 = 0.0f, c2 = 0.0f, c3 = 0.0f;
    float accR = 0.0f;

    // ---- peel stream A j = 0 (rows 0..3) ----
    {
        float4 v = __ldcs(pA);
        float s = (v.x + v.y) + (v.z + v.w);
        totA += s;
        if (q0)  { c0 += v.x; c1 += v.y; }
        if (q95) { c2 += v.z; c3 += v.w; }
        if (r0 < 2) {
            accR += s;
            if (q0)  { corn[r0*4 + 0] = v.x; corn[r0*4 + 1] = v.y; }
            if (q95) { corn[r0*4 + 2] = v.z; corn[r0*4 + 3] = v.w; }
        }
        pA += 384;
    }

    // ---- dual-stream interior: A j=1..47, B j=48..94 (47 iters each) ----
    #pragma unroll 4
    for (int j = 0; j < 47; j++) {
        float4 va = __ldcs(pA);
        float4 vb = __ldcs(pB);
        pA += 384;
        pB += 384;
        totA += (va.x + va.y) + (va.z + va.w);
        totB += (vb.x + vb.y) + (vb.z + vb.w);
        if (q0)  { c0 += va.x + vb.x; c1 += va.y + vb.y; }
        if (q95) { c2 += va.z + vb.z; c3 += va.w + vb.w; }
    }

    // ---- peel stream B j = 95 (rows 380..383) ----
    {
        float4 v = __ldcs(pB);
        float s = (v.x + v.y) + (v.z + v.w);
        totB += s;
        if (q0)  { c0 += v.x; c1 += v.y; }
        if (q95) { c2 += v.z; c3 += v.w; }
        if (r0 >= 2) {                  // rows 382 (r0=2), 383 (r0=3)
            accR += s;
            if (q0)  { corn[r0*4 + 0] = v.x; corn[r0*4 + 1] = v.y; }
            if (q95) { corn[r0*4 + 2] = v.z; corn[r0*4 + 3] = v.w; }
        }
    }

    __syncthreads();   // rowsh/colsh init + corn stores ordered

    atomicAdd(&rowsh[r0], accR);
    if (q0)  { atomicAdd(&colsh[0], c0); atomicAdd(&colsh[1], c1); }
    if (q95) { atomicAdd(&colsh[2], c2); atomicAdd(&colsh[3], c3); }

    float tot = totA + totB;
    #pragma unroll
    for (int off = 16; off > 0; off >>= 1)
        tot += __shfl_down_sync(0xffffffffu, tot, off);
    int warp = tid >> 5, lane = tid & 31;
    if (lane == 0) red[warp] = tot;
    __syncthreads();

    if (tid == 0) {
        float T = 0.0f;
        #pragma unroll
        for (int w = 0; w < 12; w++) T += red[w];
        const int ER[3][2] = { {2,3}, {0,3}, {0,1} };
        float Rex[3] = { rowsh[2]+rowsh[3], rowsh[0]+rowsh[3], rowsh[0]+rowsh[1] };
        float Cex[3] = { colsh[2]+colsh[3], colsh[0]+colsh[3], colsh[0]+colsh[1] };
        #pragma unroll
        for (int kh = 0; kh < 3; kh++) {
            #pragma unroll
            for (int kw = 0; kw < 3; kw++) {
                float cor = 0.0f;
                #pragma unroll
                for (int i = 0; i < 2; i++)
                    #pragma unroll
                    for (int j = 0; j < 2; j++)
                        cor += corn[ER[kh][i]*4 + ER[kw][j]];
                g_S[which][c][kh*3 + kw] = T - Rex[kh] - Cex[kw] + cor;
            }
        }
    }
}

// ---------------------------------------------------------------------------
// Kernel 2: per-output-channel matvec + sigmoid + branch flags -> coefficients.
// ---------------------------------------------------------------------------
__global__ void __launch_bounds__(256) coef_kernel(const float* __restrict__ W,
                                                   const float* __restrict__ b) {
    const int oc = blockIdx.x;
    const int ic = threadIdx.x;
    const float* wrow = W + (size_t)oc * CCH * 9 + ic * 9;
    float d1 = 0.0f, d2 = 0.0f;
    #pragma unroll
    for (int k = 0; k < 9; k++) {
        float w = wrow[k];
        d1 += w * g_S[0][ic][k];
        d2 += w * g_S[1][ic][k];
    }
    #pragma unroll
    for (int off = 16; off > 0; off >>= 1) {
        d1 += __shfl_down_sync(0xffffffffu, d1, off);
        d2 += __shfl_down_sync(0xffffffffu, d2, off);
    }
    __shared__ float s1[8], s2[8];
    int warp = ic >> 5, lane = ic & 31;
    if (lane == 0) { s1[warp] = d1; s2[warp] = d2; }
    __syncthreads();
    if (ic == 0) {
        float D1 = 0.0f, D2 = 0.0f;
        #pragma unroll
        for (int w = 0; w < 8; w++) { D1 += s1[w]; D2 += s2[w]; }
        float bb = b[oc];
        float m1 = bb + D1 * INVN;
        float m2 = bb + D2 * INVN;
        float m3 = bb + (D1 + D2) * INVN;
        float x1 = 1.0f / (1.0f + expf(-m1));
        float x2 = 1.0f / (1.0f + expf(-m2));
        float x3 = 1.0f / (1.0f + expf(-m3));
        bool c1 = (x1 >= x2);
        bool c2 = (x1 <= x2);
        float a1 = (c1 && (x1 >= x3)) ? 1.0f : 0.0f;
        float a2 = (c2 && (x2 >= x3)) ? 1.0f : 0.0f;
        float a3 = ((c1 && (x1 < x3)) || (c2 && (x2 < x3))) ? 1.0f : 0.0f;
        g_cf[0][oc] = a1 + a3;   // multiplies input1
        g_cf[1][oc] = a2 + a3;   // multiplies input2
    }
}

// ---------------------------------------------------------------------------
// Kernel 3: out = k1[ch]*in1 + k2[ch]*in2, float4 streaming (measured ~84% of
// HBM peak — at ceiling; unchanged from R2).
// ---------------------------------------------------------------------------
__global__ void __launch_bounds__(256) combine_kernel(const float4* __restrict__ in1,
                                                      const float4* __restrict__ in2,
                                                      float4* __restrict__ out) {
    const int ch  = blockIdx.x / (NQ / 256);          // 144 blocks per channel
    const int idx = blockIdx.x * 256 + threadIdx.x;
    const float k1 = g_cf[0][ch];
    const float k2 = g_cf[1][ch];
    float4 a = __ldcs(in1 + idx);
    float4 b = __ldcs(in2 + idx);
    float4 o;
    o.x = k1 * a.x + k2 * b.x;
    o.y = k1 * a.y + k2 * b.y;
    o.z = k1 * a.z + k2 * b.z;
    o.w = k1 * a.w + k2 * b.w;
    __stcs(out + idx, o);
}

extern "C" void kernel_launch(void* const* d_in, const int* in_sizes, int n_in,
                              void* d_out, int out_size) {
    const float* in1 = (const float*)d_in[0];
    const float* in2 = (const float*)d_in[1];
    const float* W   = (const float*)d_in[2];
    const float* b   = (const float*)d_in[3];
    float* out = (float*)d_out;

    stats_kernel<<<dim3(CCH, 2), 384>>>(in1, in2);
    coef_kernel<<<CCH, 256>>>(W, b);
    combine_kernel<<<CCH * (NQ / 256), 256>>>((const float4*)in1,
                                              (const float4*)in2,
                                              (float4*)out);
}

// round 10
// speedup vs baseline: 1.2241x; 1.0056x over previous
#include <cuda_runtime.h>
#include <math.h>

#define CCH   256
#define HW    384
#define NPIX  (HW*HW)        // 147456 elems per channel
#define NQ    (NPIX/4)       // 36864 float4 per channel
#define QPR   (HW/4)         // 96 float4 per row
#define CRES  160            // channels >= CRES are the L2-resident set (~110MB)
#define INVN  (1.0f/(382.0f*382.0f))

// Scratch: window sums S[input][channel][9] and final per-channel coefficients.
__device__ float g_S[2][CCH][9];
__device__ float g_cf[2][CCH];

template<bool KEEP>
__device__ __forceinline__ float4 LDP(const float4* __restrict__ p) {
    return KEEP ? __ldg(p) : __ldcs(p);   // resident: default L2; streaming: evict-first
}

// ---------------------------------------------------------------------------
// Stats body (templated on L2 policy). 384 threads: r0=tid/96, q=tid%96.
// Dual stream: A rows [0,192), B rows [192,384). Border peels on A j=0 / B j=95.
// ---------------------------------------------------------------------------
template<bool KEEP>
__device__ __forceinline__ void stats_body(const float4* __restrict__ x,
                                           int which, int c, int tid,
                                           float* corn, float* rowsh,
                                           float* colsh, float* red) {
    const int r0  = tid / 96;          // 0..3
    const int q   = tid - r0 * 96;     // 0..95
    const bool q0  = (q == 0);
    const bool q95 = (q == 95);

    const float4* pA = x + (size_t)(r0 * 96 + q);            // row r0
    const float4* pB = x + (size_t)((192 + r0) * 96 + q);    // row 192+r0

    float totA = 0.0f, totB = 0.0f;
    float c0 = 0.0f, c1 = 0.0f, c2 = 0.0f, c3 = 0.0f;
    float accR = 0.0f;

    // ---- peel stream A j = 0 (rows 0..3) ----
    {
        float4 v = LDP<KEEP>(pA);
        float s = (v.x + v.y) + (v.z + v.w);
        totA += s;
        if (q0)  { c0 += v.x; c1 += v.y; }
        if (q95) { c2 += v.z; c3 += v.w; }
        if (r0 < 2) {
            accR += s;
            if (q0)  { corn[r0*4 + 0] = v.x; corn[r0*4 + 1] = v.y; }
            if (q95) { corn[r0*4 + 2] = v.z; corn[r0*4 + 3] = v.w; }
        }
        pA += 384;
    }

    // ---- dual-stream interior: A j=1..47, B j=48..94 ----
    #pragma unroll 4
    for (int j = 0; j < 47; j++) {
        float4 va = LDP<KEEP>(pA);
        float4 vb = LDP<KEEP>(pB);
        pA += 384;
        pB += 384;
        totA += (va.x + va.y) + (va.z + va.w);
        totB += (vb.x + vb.y) + (vb.z + vb.w);
        if (q0)  { c0 += va.x + vb.x; c1 += va.y + vb.y; }
        if (q95) { c2 += va.z + vb.z; c3 += va.w + vb.w; }
    }

    // ---- peel stream B j = 95 (rows 380..383) ----
    {
        float4 v = LDP<KEEP>(pB);
        float s = (v.x + v.y) + (v.z + v.w);
        totB += s;
        if (q0)  { c0 += v.x; c1 += v.y; }
        if (q95) { c2 += v.z; c3 += v.w; }
        if (r0 >= 2) {
            accR += s;
            if (q0)  { corn[r0*4 + 0] = v.x; corn[r0*4 + 1] = v.y; }
            if (q95) { corn[r0*4 + 2] = v.z; corn[r0*4 + 3] = v.w; }
        }
    }

    __syncthreads();   // rowsh/colsh init + corn stores ordered

    atomicAdd(&rowsh[r0], accR);
    if (q0)  { atomicAdd(&colsh[0], c0); atomicAdd(&colsh[1], c1); }
    if (q95) { atomicAdd(&colsh[2], c2); atomicAdd(&colsh[3], c3); }

    float tot = totA + totB;
    #pragma unroll
    for (int off = 16; off > 0; off >>= 1)
        tot += __shfl_down_sync(0xffffffffu, tot, off);
    int warp = tid >> 5, lane = tid & 31;
    if (lane == 0) red[warp] = tot;
    __syncthreads();

    if (tid == 0) {
        float T = 0.0f;
        #pragma unroll
        for (int w = 0; w < 12; w++) T += red[w];
        const int ER[3][2] = { {2,3}, {0,3}, {0,1} };
        float Rex[3] = { rowsh[2]+rowsh[3], rowsh[0]+rowsh[3], rowsh[0]+rowsh[1] };
        float Cex[3] = { colsh[2]+colsh[3], colsh[0]+colsh[3], colsh[0]+colsh[1] };
        #pragma unroll
        for (int kh = 0; kh < 3; kh++) {
            #pragma unroll
            for (int kw = 0; kw < 3; kw++) {
                float cor = 0.0f;
                #pragma unroll
                for (int i = 0; i < 2; i++)
                    #pragma unroll
                    for (int j = 0; j < 2; j++)
                        cor += corn[ER[kh][i]*4 + ER[kw][j]];
                g_S[which][c][kh*3 + kw] = T - Rex[kh] - Cex[kw] + cor;
            }
        }
    }
}

__global__ void __launch_bounds__(384) stats_kernel(const float* __restrict__ in1,
                                                    const float* __restrict__ in2) {
    const int c     = blockIdx.x;
    const int which = blockIdx.y;
    const float4* x = ((const float4*)(which ? in2 : in1)) + (size_t)c * NQ;
    const int tid = threadIdx.x;

    __shared__ float corn[16];
    __shared__ float rowsh[4];
    __shared__ float colsh[4];
    __shared__ float red[12];
    if (tid < 4) { rowsh[tid] = 0.0f; colsh[tid] = 0.0f; }

    if (c >= CRES) stats_body<true >(x, which, c, tid, corn, rowsh, colsh, red);
    else           stats_body<false>(x, which, c, tid, corn, rowsh, colsh, red);
}

// ---------------------------------------------------------------------------
// Kernel 2: per-output-channel matvec + sigmoid + branch flags -> coefficients.
// ---------------------------------------------------------------------------
__global__ void __launch_bounds__(256) coef_kernel(const float* __restrict__ W,
                                                   const float* __restrict__ b) {
    const int oc = blockIdx.x;
    const int ic = threadIdx.x;
    const float* wrow = W + (size_t)oc * CCH * 9 + ic * 9;
    float d1 = 0.0f, d2 = 0.0f;
    #pragma unroll
    for (int k = 0; k < 9; k++) {
        float w = wrow[k];
        d1 += w * g_S[0][ic][k];
        d2 += w * g_S[1][ic][k];
    }
    #pragma unroll
    for (int off = 16; off > 0; off >>= 1) {
        d1 += __shfl_down_sync(0xffffffffu, d1, off);
        d2 += __shfl_down_sync(0xffffffffu, d2, off);
    }
    __shared__ float s1[8], s2[8];
    int warp = ic >> 5, lane = ic & 31;
    if (lane == 0) { s1[warp] = d1; s2[warp] = d2; }
    __syncthreads();
    if (ic == 0) {
        float D1 = 0.0f, D2 = 0.0f;
        #pragma unroll
        for (int w = 0; w < 8; w++) { D1 += s1[w]; D2 += s2[w]; }
        float bb = b[oc];
        float m1 = bb + D1 * INVN;
        float m2 = bb + D2 * INVN;
        float m3 = bb + (D1 + D2) * INVN;
        float x1 = 1.0f / (1.0f + expf(-m1));
        float x2 = 1.0f / (1.0f + expf(-m2));
        float x3 = 1.0f / (1.0f + expf(-m3));
        bool c1 = (x1 >= x2);
        bool c2 = (x1 <= x2);
        float a1 = (c1 && (x1 >= x3)) ? 1.0f : 0.0f;
        float a2 = (c2 && (x2 >= x3)) ? 1.0f : 0.0f;
        float a3 = ((c1 && (x1 < x3)) || (c2 && (x2 < x3))) ? 1.0f : 0.0f;
        g_cf[0][oc] = a1 + a3;   // multiplies input1
        g_cf[1][oc] = a2 + a3;   // multiplies input2
    }
}

// ---------------------------------------------------------------------------
// Kernel 3: out = k1[ch]*in1 + k2[ch]*in2. Channels DESCENDING so the
// L2-resident set (ch >= CRES, refreshed at stats' tail) is read first and
// with default policy (stays resident for the next graph replay). Streaming
// channels use evict-first loads; all stores evict-first.
// ---------------------------------------------------------------------------
__global__ void __launch_bounds__(256) combine_kernel(const float4* __restrict__ in1,
                                                      const float4* __restrict__ in2,
                                                      float4* __restrict__ out) {
    const int bpc   = NQ / 256;                    // 144 blocks per channel
    const int ch    = (CCH - 1) - blockIdx.x / bpc;
    const int inCh  = (blockIdx.x % bpc) * 256 + threadIdx.x;
    const size_t idx = (size_t)ch * NQ + inCh;
    const float k1 = g_cf[0][ch];
    const float k2 = g_cf[1][ch];
    float4 a, b;
    if (ch >= CRES) { a = __ldg(in1 + idx);  b = __ldg(in2 + idx); }
    else            { a = __ldcs(in1 + idx); b = __ldcs(in2 + idx); }
    float4 o;
    o.x = k1 * a.x + k2 * b.x;
    o.y = k1 * a.y + k2 * b.y;
    o.z = k1 * a.z + k2 * b.z;
    o.w = k1 * a.w + k2 * b.w;
    __stcs(out + idx, o);
}

extern "C" void kernel_launch(void* const* d_in, const int* in_sizes, int n_in,
                              void* d_out, int out_size) {
    const float* in1 = (const float*)d_in[0];
    const float* in2 = (const float*)d_in[1];
    const float* W   = (const float*)d_in[2];
    const float* b   = (const float*)d_in[3];
    float* out = (float*)d_out;

    stats_kernel<<<dim3(CCH, 2), 384>>>(in1, in2);
    coef_kernel<<<CCH, 256>>>(W, b);
    combine_kernel<<<CCH * (NQ / 256), 256>>>((const float4*)in1,
                                              (const float4*)in2,
                                              (float4*)out);
}

// round 11
// speedup vs baseline: 1.3157x; 1.0748x over previous
#include <cuda_runtime.h>
#include <math.h>

#define CCH   256
#define HW    384
#define NPIX  (HW*HW)        // 147456 elems per channel
#define NQ    (NPIX/4)       // 36864 float4 per channel
#define QPR   (HW/4)         // 96 float4 per row
#define INVN  (1.0f/(382.0f*382.0f))

// Scratch: window sums S[input][channel][9] and final per-channel coefficients.
__device__ float g_S[2][CCH][9];
__device__ float g_cf[2][CCH];

// ---------------------------------------------------------------------------
// Kernel 1: per-(input, channel) statistics -> 9 window sums.
// 384 threads: r0 = tid/96 in [0,4), q = tid%96. Dual stream A/B halves.
// (Best measured shape: ~54us, pinned at ~5.7TB/s for this access pattern.)
// ---------------------------------------------------------------------------
__global__ void __launch_bounds__(384) stats_kernel(const float* __restrict__ in1,
                                                    const float* __restrict__ in2) {
    const int c     = blockIdx.x;
    const int which = blockIdx.y;
    const float4* x = ((const float4*)(which ? in2 : in1)) + (size_t)c * NQ;

    const int tid = threadIdx.x;
    const int r0  = tid / 96;          // 0..3
    const int q   = tid - r0 * 96;     // 0..95
    const bool q0  = (q == 0);
    const bool q95 = (q == 95);

    __shared__ float corn[16];
    __shared__ float rowsh[4];
    __shared__ float colsh[4];
    __shared__ float red[12];
    if (tid < 4) { rowsh[tid] = 0.0f; colsh[tid] = 0.0f; }

    const float4* pA = x + (size_t)(r0 * 96 + q);            // row r0
    const float4* pB = x + (size_t)((192 + r0) * 96 + q);    // row 192+r0

    float totA = 0.0f, totB = 0.0f;
    float c0 = 0.0f, c1 = 0.0f, c2 = 0.0f, c3 = 0.0f;
    float accR = 0.0f;

    // ---- peel stream A j = 0 (rows 0..3) ----
    {
        float4 v = __ldcs(pA);
        float s = (v.x + v.y) + (v.z + v.w);
        totA += s;
        if (q0)  { c0 += v.x; c1 += v.y; }
        if (q95) { c2 += v.z; c3 += v.w; }
        if (r0 < 2) {
            accR += s;
            if (q0)  { corn[r0*4 + 0] = v.x; corn[r0*4 + 1] = v.y; }
            if (q95) { corn[r0*4 + 2] = v.z; corn[r0*4 + 3] = v.w; }
        }
        pA += 384;
    }

    // ---- dual-stream interior: A j=1..47, B j=48..94 ----
    #pragma unroll 4
    for (int j = 0; j < 47; j++) {
        float4 va = __ldcs(pA);
        float4 vb = __ldcs(pB);
        pA += 384;
        pB += 384;
        totA += (va.x + va.y) + (va.z + va.w);
        totB += (vb.x + vb.y) + (vb.z + vb.w);
        if (q0)  { c0 += va.x + vb.x; c1 += va.y + vb.y; }
        if (q95) { c2 += va.z + vb.z; c3 += va.w + vb.w; }
    }

    // ---- peel stream B j = 95 (rows 380..383) ----
    {
        float4 v = __ldcs(pB);
        float s = (v.x + v.y) + (v.z + v.w);
        totB += s;
        if (q0)  { c0 += v.x; c1 += v.y; }
        if (q95) { c2 += v.z; c3 += v.w; }
        if (r0 >= 2) {
            accR += s;
            if (q0)  { corn[r0*4 + 0] = v.x; corn[r0*4 + 1] = v.y; }
            if (q95) { corn[r0*4 + 2] = v.z; corn[r0*4 + 3] = v.w; }
        }
    }

    __syncthreads();   // rowsh/colsh init + corn stores ordered

    atomicAdd(&rowsh[r0], accR);
    if (q0)  { atomicAdd(&colsh[0], c0); atomicAdd(&colsh[1], c1); }
    if (q95) { atomicAdd(&colsh[2], c2); atomicAdd(&colsh[3], c3); }

    float tot = totA + totB;
    #pragma unroll
    for (int off = 16; off > 0; off >>= 1)
        tot += __shfl_down_sync(0xffffffffu, tot, off);
    int warp = tid >> 5, lane = tid & 31;
    if (lane == 0) red[warp] = tot;
    __syncthreads();

    if (tid == 0) {
        float T = 0.0f;
        #pragma unroll
        for (int w = 0; w < 12; w++) T += red[w];
        const int ER[3][2] = { {2,3}, {0,3}, {0,1} };
        float Rex[3] = { rowsh[2]+rowsh[3], rowsh[0]+rowsh[3], rowsh[0]+rowsh[1] };
        float Cex[3] = { colsh[2]+colsh[3], colsh[0]+colsh[3], colsh[0]+colsh[1] };
        #pragma unroll
        for (int kh = 0; kh < 3; kh++) {
            #pragma unroll
            for (int kw = 0; kw < 3; kw++) {
                float cor = 0.0f;
                #pragma unroll
                for (int i = 0; i < 2; i++)
                    #pragma unroll
                    for (int j = 0; j < 2; j++)
                        cor += corn[ER[kh][i]*4 + ER[kw][j]];
                g_S[which][c][kh*3 + kw] = T - Rex[kh] - Cex[kw] + cor;
            }
        }
    }
}

// ---------------------------------------------------------------------------
// Kernel 2: per-output-channel matvec + sigmoid + branch flags -> coefficients.
// ---------------------------------------------------------------------------
__global__ void __launch_bounds__(256) coef_kernel(const float* __restrict__ W,
                                                   const float* __restrict__ b) {
    const int oc = blockIdx.x;
    const int ic = threadIdx.x;
    const float* wrow = W + (size_t)oc * CCH * 9 + ic * 9;
    float d1 = 0.0f, d2 = 0.0f;
    #pragma unroll
    for (int k = 0; k < 9; k++) {
        float w = wrow[k];
        d1 += w * g_S[0][ic][k];
        d2 += w * g_S[1][ic][k];
    }
    #pragma unroll
    for (int off = 16; off > 0; off >>= 1) {
        d1 += __shfl_down_sync(0xffffffffu, d1, off);
        d2 += __shfl_down_sync(0xffffffffu, d2, off);
    }
    __shared__ float s1[8], s2[8];
    int warp = ic >> 5, lane = ic & 31;
    if (lane == 0) { s1[warp] = d1; s2[warp] = d2; }
    __syncthreads();
    if (ic == 0) {
        float D1 = 0.0f, D2 = 0.0f;
        #pragma unroll
        for (int w = 0; w < 8; w++) { D1 += s1[w]; D2 += s2[w]; }
        float bb = b[oc];
        float m1 = bb + D1 * INVN;
        float m2 = bb + D2 * INVN;
        float m3 = bb + (D1 + D2) * INVN;
        float x1 = 1.0f / (1.0f + expf(-m1));
        float x2 = 1.0f / (1.0f + expf(-m2));
        float x3 = 1.0f / (1.0f + expf(-m3));
        bool c1 = (x1 >= x2);
        bool c2 = (x1 <= x2);
        float a1 = (c1 && (x1 >= x3)) ? 1.0f : 0.0f;
        float a2 = (c2 && (x2 >= x3)) ? 1.0f : 0.0f;
        float a3 = ((c1 && (x1 < x3)) || (c2 && (x2 < x3))) ? 1.0f : 0.0f;
        g_cf[0][oc] = a1 + a3;   // multiplies input1
        g_cf[1][oc] = a2 + a3;   // multiplies input2
    }
}

// ---------------------------------------------------------------------------
// Kernel 3: out = k1[ch]*in1 + k2[ch]*in2 with LOAD SKIPPING.
// (k1,k2) is one of (1,0),(0,1),(1,1): when a coefficient is exactly 0 the
// corresponding input is never loaded. Branch is block-uniform (one channel
// per block) and deterministic for fixed inputs -> graph-safe. Expected for
// random inputs: ~25% of channels skip in2, ~25% skip in1 -> ~25% fewer
// combine-pass DRAM reads.
// ---------------------------------------------------------------------------
__global__ void __launch_bounds__(256) combine_kernel(const float4* __restrict__ in1,
                                                      const float4* __restrict__ in2,
                                                      float4* __restrict__ out) {
    const int ch  = blockIdx.x / (NQ / 256);          // 144 blocks per channel
    const int idx = blockIdx.x * 256 + threadIdx.x;
    const float k1 = g_cf[0][ch];
    const float k2 = g_cf[1][ch];
    float4 o;
    if (k2 == 0.0f) {                 // (1,0): only input1 needed
        float4 a = __ldcs(in1 + idx);
        o.x = k1 * a.x; o.y = k1 * a.y; o.z = k1 * a.z; o.w = k1 * a.w;
    } else if (k1 == 0.0f) {          // (0,1): only input2 needed
        float4 b = __ldcs(in2 + idx);
        o.x = k2 * b.x; o.y = k2 * b.y; o.z = k2 * b.z; o.w = k2 * b.w;
    } else {                          // (1,1): both
        float4 a = __ldcs(in1 + idx);
        float4 b = __ldcs(in2 + idx);
        o.x = k1 * a.x + k2 * b.x;
        o.y = k1 * a.y + k2 * b.y;
        o.z = k1 * a.z + k2 * b.z;
        o.w = k1 * a.w + k2 * b.w;
    }
    __stcs(out + idx, o);
}

extern "C" void kernel_launch(void* const* d_in, const int* in_sizes, int n_in,
                              void* d_out, int out_size) {
    const float* in1 = (const float*)d_in[0];
    const float* in2 = (const float*)d_in[1];
    const float* W   = (const float*)d_in[2];
    const float* b   = (const float*)d_in[3];
    float* out = (float*)d_out;

    stats_kernel<<<dim3(CCH, 2), 384>>>(in1, in2);
    coef_kernel<<<CCH, 256>>>(W, b);
    combine_kernel<<<CCH * (NQ / 256), 256>>>((const float4*)in1,
                                              (const float4*)in2,
                                              (float4*)out);
}